// round 16
// baseline (speedup 1.0000x reference)
#include <cuda_runtime.h>
#include <math.h>
#include <stdint.h>

#define BATCH 8
#define N     2048
#define TPB   256
#define RPC   32
#define INVL  20.0f
#define NITER 10

#define CAP   320                   // sparse slots per row (multiple of 64)
#define LCUT  (-27.0f)              // log-domain cutoff (e^-27)
#define NROWS (BATCH * N)           // 16384
#define GRID_BIG (NROWS / RPC)      // 512
#define RPW4  4                     // rows per warp

// scratch (__device__ globals; no allocation allowed)
__device__ float g_m[NROWS];
__device__ float g_s[NROWS];                 // s^(10)
__device__ float g_acc[NITER + 1][NROWS];    // column accumulators per iteration
__device__ int2  g_sent[(size_t)NROWS * CAP];// (col, val-bits) AoS entries
__device__ int   g_scnt[NROWS];              // padded counts (multiple of 64)

__global__ void zero_kernel() {
    int idx = blockIdx.x * TPB + threadIdx.x;
    if (idx < NITER * NROWS) (&g_acc[1][0])[idx] = 0.0f;
}

// K1 = iteration 1, warp-per-row (R14 structure, int2 output):
//   m_i = rowmax(A*INVL); s1 = 1/rowsum (entries > LCUT);
//   extract entries via per-warp smem counters; acc1 += e*s1 (sparse REDG).
__global__ void __launch_bounds__(TPB) k1_kernel(const float* __restrict__ A) {
    __shared__ int scnt_sm[RPC];                 // per-row counters, warp-private
    const int tid = threadIdx.x, wid = tid >> 5, lane = tid & 31;
    if (lane < RPW4) scnt_sm[wid * RPW4 + lane] = 0;
    __syncwarp();

    const int rbase = blockIdx.x * RPC + wid * RPW4;
    const int b = rbase >> 11;
    float* acc1 = &g_acc[1][b * N];

    #pragma unroll 1
    for (int r = 0; r < RPW4; r++) {
        const int row = rbase + r;
        const float4* ap = (const float4*)(A + (size_t)row * N);

        float4 v[16];
        #pragma unroll
        for (int i = 0; i < 16; i++) v[i] = ap[i * 32 + lane];   // col=(i*32+lane)*4+j

        float m = -INFINITY;
        #pragma unroll
        for (int i = 0; i < 16; i++) {
            v[i].x *= INVL; v[i].y *= INVL; v[i].z *= INVL; v[i].w *= INVL;
            m = fmaxf(m, fmaxf(fmaxf(v[i].x, v[i].y), fmaxf(v[i].z, v[i].w)));
        }
        #pragma unroll
        for (int o = 16; o; o >>= 1) m = fmaxf(m, __shfl_xor_sync(0xffffffffu, m, o));

        // exp only above threshold; keep e in v; lane-sum
        float sum = 0.0f;
        #pragma unroll
        for (int i = 0; i < 16; i++) {
            float* p = (float*)&v[i];
            #pragma unroll
            for (int j = 0; j < 4; j++) {
                const float d = p[j] - m;
                float e = 0.0f;
                if (d > LCUT) { e = __expf(d); sum += e; }
                p[j] = e;
            }
        }
        #pragma unroll
        for (int o = 16; o; o >>= 1) sum += __shfl_xor_sync(0xffffffffu, sum, o);
        const float s1 = 1.0f / sum;
        if (lane == 0) g_m[row] = m;

        // extraction (per-warp smem counter) + sparse acc1 scatter
        const int cidx = wid * RPW4 + r;
        const size_t rofs = (size_t)row * CAP;
        #pragma unroll
        for (int i = 0; i < 16; i++) {
            const float* p = (const float*)&v[i];
            #pragma unroll
            for (int j = 0; j < 4; j++) {
                const float e = p[j];
                if (e > 0.0f) {
                    const int col = (i * 32 + lane) * 4 + j;
                    const int idx = atomicAdd(&scnt_sm[cidx], 1);
                    if (idx < CAP)
                        g_sent[rofs + idx] = make_int2(col, __float_as_int(e));
                    atomicAdd(acc1 + col, e * s1);
                }
            }
        }
        __syncwarp();
        // pad to multiple of 64
        const int c = min(scnt_sm[cidx], CAP);
        const int cpad = min((c + 63) & ~63, CAP);
        for (int s = c + lane; s < cpad; s += 32)
            g_sent[rofs + s] = make_int2(0, 0);
        if (lane == 0) g_scnt[row] = cpad;
        __syncwarp();
    }
}

// K2..K10 sparse (R13-proven, verbatim): CTA = 32 rows (one batch);
// tau inverted in smem; gathers via LDS; scatters via global REDs.
__global__ void __launch_bounds__(TPB) sparse_iter(int k) {
    __shared__ float s_tau[N];                           // 8 KB
    const int tid = threadIdx.x, wid = tid >> 5, lane = tid & 31;
    const int rcta = blockIdx.x * RPC;
    const int b = rcta >> 11;
    const float* __restrict__ accp = &g_acc[k - 1][b * N];
    float* accn = &g_acc[k][b * N];

    {   // stage tau = 1/acc[k-1] (coalesced)
        const int i0 = tid * 8;
        float4 a0 = *(const float4*)(accp + i0);
        float4 a1 = *(const float4*)(accp + i0 + 4);
        float4 t0 = {1.0f / fmaxf(a0.x, 1e-30f), 1.0f / fmaxf(a0.y, 1e-30f),
                     1.0f / fmaxf(a0.z, 1e-30f), 1.0f / fmaxf(a0.w, 1e-30f)};
        float4 t1 = {1.0f / fmaxf(a1.x, 1e-30f), 1.0f / fmaxf(a1.y, 1e-30f),
                     1.0f / fmaxf(a1.z, 1e-30f), 1.0f / fmaxf(a1.w, 1e-30f)};
        *(float4*)&s_tau[i0] = t0;
        *(float4*)&s_tau[i0 + 4] = t1;
    }
    __syncthreads();

    const int rbase = rcta + wid * RPW4;                 // this warp's 4 rows
    int2 e0[RPW4], e1[RPW4];
    int cnt[RPW4];
    #pragma unroll
    for (int r = 0; r < RPW4; r++) {
        const int2* sp = &g_sent[(size_t)(rbase + r) * CAP];
        e0[r] = sp[lane];
        e1[r] = sp[lane + 32];
        cnt[r] = g_scnt[rbase + r];
    }
    float v0[RPW4], v1[RPW4], dot[RPW4];
    #pragma unroll
    for (int r = 0; r < RPW4; r++) {
        v0[r] = __int_as_float(e0[r].y);
        v1[r] = __int_as_float(e1[r].y);
        dot[r] = v0[r] * s_tau[e0[r].x] + v1[r] * s_tau[e1[r].x];
    }
    #pragma unroll
    for (int r = 0; r < RPW4; r++) {
        if (cnt[r] > 64) {
            const int2* sp = &g_sent[(size_t)(rbase + r) * CAP];
            #pragma unroll 1
            for (int s = lane + 64; s < cnt[r]; s += 64) {
                const int2 f0 = sp[s], f1 = sp[s + 32];
                dot[r] += __int_as_float(f0.y) * s_tau[f0.x]
                        + __int_as_float(f1.y) * s_tau[f1.x];
            }
        }
    }
    #pragma unroll
    for (int o = 16; o; o >>= 1) {
        #pragma unroll
        for (int r = 0; r < RPW4; r++)
            dot[r] += __shfl_xor_sync(0xffffffffu, dot[r], o);
    }
    float sig[RPW4];
    #pragma unroll
    for (int r = 0; r < RPW4; r++) sig[r] = 1.0f / dot[r];

    if (k == NITER && lane < RPW4)
        g_s[rbase + lane] = sig[0] * (lane == 0) + sig[1] * (lane == 1)
                          + sig[2] * (lane == 2) + sig[3] * (lane == 3);

    #pragma unroll
    for (int r = 0; r < RPW4; r++) {
        if (v0[r] > 0.0f) atomicAdd(accn + e0[r].x, v0[r] * sig[r]);
        if (v1[r] > 0.0f) atomicAdd(accn + e1[r].x, v1[r] * sig[r]);
    }
    #pragma unroll
    for (int r = 0; r < RPW4; r++) {
        if (cnt[r] > 64) {
            const int2* sp = &g_sent[(size_t)(rbase + r) * CAP];
            #pragma unroll 1
            for (int s = lane + 64; s < cnt[r]; s += 64) {
                const int2 f0 = sp[s], f1 = sp[s + 32];
                const float w0 = __int_as_float(f0.y), w1 = __int_as_float(f1.y);
                if (w0 > 0.0f) atomicAdd(accn + f0.x, w0 * sig[r]);
                if (w1 > 0.0f) atomicAdd(accn + f1.x, w1 * sig[r]);
            }
        }
    }
}

// K11: out = exp(A*INVL - m_i) * s10_i * t10_j (0 below threshold). 2-row prefetch.
__global__ void __launch_bounds__(TPB) final_kernel(const float* __restrict__ A,
                                                    float* __restrict__ out) {
    const int rbase = blockIdx.x * 8;
    const int b = rbase >> 11;
    const int col = threadIdx.x * 8;
    const float* accp = &g_acc[NITER][b * N + col];
    float tv[8];
    #pragma unroll
    for (int j = 0; j < 8; j++) tv[j] = 1.0f / fmaxf(accp[j], 1e-30f);

    const size_t off0 = (size_t)rbase * N + col;
    float4 x0 = *(const float4*)(A + off0);
    float4 x1 = *(const float4*)(A + off0 + 4);

    #pragma unroll 1
    for (int r = 0; r < 8; r++) {
        float4 n0, n1;
        if (r < 7) {
            const size_t offn = (size_t)(rbase + r + 1) * N + col;
            n0 = *(const float4*)(A + offn);
            n1 = *(const float4*)(A + offn + 4);
        }
        const int row = rbase + r;
        const float s = g_s[row];
        const float m = g_m[row];
        float a[8] = {x0.x, x0.y, x0.z, x0.w, x1.x, x1.y, x1.z, x1.w};
        float o[8];
        #pragma unroll
        for (int j = 0; j < 8; j++) {
            const float d = fmaf(a[j], INVL, -m);
            o[j] = (d > LCUT) ? __expf(d) * s * tv[j] : 0.0f;
        }
        const size_t off = (size_t)row * N + col;
        *(float4*)(out + off)     = make_float4(o[0], o[1], o[2], o[3]);
        *(float4*)(out + off + 4) = make_float4(o[4], o[5], o[6], o[7]);
        x0 = n0; x1 = n1;
    }
}

extern "C" void kernel_launch(void* const* d_in, const int* in_sizes, int n_in,
                              void* d_out, int out_size) {
    const float* A = (const float*)d_in[0];
    float* O = (float*)d_out;

    zero_kernel<<<(NITER * NROWS + TPB - 1) / TPB, TPB>>>();
    k1_kernel<<<GRID_BIG, TPB>>>(A);
    for (int k = 2; k <= NITER; k++)
        sparse_iter<<<NROWS / RPC, TPB>>>(k);
    final_kernel<<<(BATCH * N) / 8, TPB>>>(A, O);
}

// round 17
// speedup vs baseline: 1.1037x; 1.1037x over previous
#include <cuda_runtime.h>
#include <math.h>
#include <stdint.h>

#define BATCH 8
#define N     2048
#define TPB   256
#define RPC   32
#define NBLK  (N / RPC)             // 64
#define GRID_BIG (NROWS / RPC)      // 512
#define INVL  20.0f
#define NITER 10

#define CAP   320                   // sparse slots per row (multiple of 64)
#define CUT   1.879529e-12f         // e^-27
#define NROWS (BATCH * N)           // 16384
#define RPW4  4                     // rows per warp
#define NCTA  (NROWS / RPC)         // 512 persistent CTAs

// scratch (__device__ globals; no allocation allowed)
__device__ float g_m[NROWS];
__device__ float g_s[NROWS];                 // s^(10)
__device__ float g_acc[NITER + 1][NROWS];    // column accumulators per iteration
__device__ int2  g_sent[(size_t)NROWS * CAP];// (col, val-bits) AoS entries
__device__ int   g_scnt[NROWS];              // padded counts (multiple of 64)
__device__ int   g_bar;                      // grid barrier counter

__global__ void zero_kernel() {
    int idx = blockIdx.x * TPB + threadIdx.x;
    if (idx < NITER * NROWS) (&g_acc[1][0])[idx] = 0.0f;
    if (idx == 0) g_bar = 0;
}

__device__ __forceinline__ void warp_red2(float& l0, float& l1) {
    #pragma unroll
    for (int o = 16; o; o >>= 1) {
        l0 += __shfl_xor_sync(0xffffffffu, l0, o);
        l1 += __shfl_xor_sync(0xffffffffu, l1, o);
    }
}

__device__ __forceinline__ void bar_arrive_release(int* p) {
    asm volatile("red.release.gpu.global.add.s32 [%0], 1;" :: "l"(p) : "memory");
}
__device__ __forceinline__ int bar_ld_acquire(const int* p) {
    int v;
    asm volatile("ld.acquire.gpu.global.s32 %0, [%1];" : "=r"(v) : "l"(p) : "memory");
    return v;
}

// K1 (R13-proven, verbatim) = iteration 1 fp32 from A: m, s1, dense acc1 colsum,
// sparse extraction with padding to multiples of 64.
__global__ void __launch_bounds__(TPB) k1_kernel(const float* __restrict__ A) {
    const int blk = blockIdx.x, b = blk / NBLK, rb = blk % NBLK;
    const int tid = threadIdx.x, wid = tid >> 5, lane = tid & 31;
    const int col = tid * 8;
    const size_t base = (size_t)b * N * N;
    __shared__ float redA[8][2], redB[8][2];
    __shared__ int scnt_sm[RPC];
    if (tid < RPC) scnt_sm[tid] = 0;
    float cp[8] = {0, 0, 0, 0, 0, 0, 0, 0};

    #pragma unroll 1
    for (int p = 0; p < RPC / 2; p++) {
        const int r0 = rb * RPC + 2 * p;
        const float4* a0p = (const float4*)(A + base + (size_t)r0 * N + col);
        const float4* a1p = (const float4*)(A + base + (size_t)(r0 + 1) * N + col);
        float4 x0 = a0p[0], x1 = a0p[1], y0 = a1p[0], y1 = a1p[1];
        float a0[8] = {x0.x, x0.y, x0.z, x0.w, x1.x, x1.y, x1.z, x1.w};
        float a1[8] = {y0.x, y0.y, y0.z, y0.w, y1.x, y1.y, y1.z, y1.w};
        float m0 = -INFINITY, m1 = -INFINITY;
        #pragma unroll
        for (int k = 0; k < 8; k++) {
            a0[k] *= INVL; a1[k] *= INVL;
            m0 = fmaxf(m0, a0[k]); m1 = fmaxf(m1, a1[k]);
        }
        #pragma unroll
        for (int o = 16; o; o >>= 1) {
            m0 = fmaxf(m0, __shfl_xor_sync(0xffffffffu, m0, o));
            m1 = fmaxf(m1, __shfl_xor_sync(0xffffffffu, m1, o));
        }
        if (lane == 0) { redA[wid][0] = m0; redA[wid][1] = m1; }
        __syncthreads();
        m0 = redA[0][0]; m1 = redA[0][1];
        #pragma unroll
        for (int w = 1; w < 8; w++) { m0 = fmaxf(m0, redA[w][0]); m1 = fmaxf(m1, redA[w][1]); }

        float e0[8], e1[8], l0 = 0.0f, l1 = 0.0f;
        #pragma unroll
        for (int k = 0; k < 8; k++) {
            e0[k] = __expf(a0[k] - m0); e1[k] = __expf(a1[k] - m1);
            l0 += e0[k]; l1 += e1[k];
        }

        const size_t rid0 = (size_t)(b * N + r0);
        #pragma unroll
        for (int k = 0; k < 8; k++) {
            if (e0[k] > CUT) {
                int idx = atomicAdd(&scnt_sm[2 * p], 1);
                if (idx < CAP)
                    g_sent[rid0 * CAP + idx] = make_int2(col + k, __float_as_int(e0[k]));
            }
            if (e1[k] > CUT) {
                int idx = atomicAdd(&scnt_sm[2 * p + 1], 1);
                if (idx < CAP)
                    g_sent[(rid0 + 1) * CAP + idx] = make_int2(col + k, __float_as_int(e1[k]));
            }
        }

        warp_red2(l0, l1);
        if (lane == 0) { redB[wid][0] = l0; redB[wid][1] = l1; }
        __syncthreads();
        l0 = redB[0][0]; l1 = redB[0][1];
        #pragma unroll
        for (int w = 1; w < 8; w++) { l0 += redB[w][0]; l1 += redB[w][1]; }
        const float s0 = 1.0f / l0, s1 = 1.0f / l1;
        if (tid == 0) { g_m[b * N + r0] = m0; g_m[b * N + r0 + 1] = m1; }
        #pragma unroll
        for (int k = 0; k < 8; k++) {
            cp[k] = fmaf(e0[k], s0, cp[k]);
            cp[k] = fmaf(e1[k], s1, cp[k]);
        }
    }
    float* acc = &g_acc[1][b * N + col];
    #pragma unroll
    for (int k = 0; k < 8; k++) atomicAdd(acc + k, cp[k]);

    __syncthreads();
    {
        const int r = tid >> 3, t8 = tid & 7;
        const int c = min(scnt_sm[r], CAP);
        const int cpad = (c + 63) & ~63;                   // 64..320
        const size_t rbase = (size_t)(b * N + rb * RPC + r) * CAP;
        for (int s = c + t8; s < cpad; s += 8)
            g_sent[rbase + s] = make_int2(0, 0);
        if (t8 == 0) g_scnt[b * N + rb * RPC + r] = cpad;
    }
}

// Persistent sparse: iterations 2..10 in ONE launch.
// Per iteration: grid barrier -> tau staged (ldcg + rcp) in smem -> R13 gather/scatter.
// Entry lists loaded into registers ONCE for all 9 iterations.
__global__ void __launch_bounds__(TPB, 4) sparse_persist() {
    __shared__ float s_tau[N];                           // 8 KB
    const int tid = threadIdx.x, wid = tid >> 5, lane = tid & 31;
    const int rcta = blockIdx.x * RPC;
    const int b = rcta >> 11;

    // entry lists: load once, keep in registers across all iterations
    const int rbase = rcta + wid * RPW4;
    int2 e0[RPW4], e1[RPW4];
    int cnt[RPW4];
    #pragma unroll
    for (int r = 0; r < RPW4; r++) {
        const int2* sp = &g_sent[(size_t)(rbase + r) * CAP];
        e0[r] = sp[lane];
        e1[r] = sp[lane + 32];
        cnt[r] = g_scnt[rbase + r];
    }
    float v0[RPW4], v1[RPW4];
    #pragma unroll
    for (int r = 0; r < RPW4; r++) {
        v0[r] = __int_as_float(e0[r].y);
        v1[r] = __int_as_float(e1[r].y);
    }

    #pragma unroll 1
    for (int k = 2; k <= NITER; k++) {
        // wait for all scatters of iteration k-1 (not needed for k==2: k1 done at launch)
        if (k > 2) {
            if (tid == 0) {
                const int target = NCTA * (k - 2);
                while (bar_ld_acquire(&g_bar) < target) __nanosleep(32);
            }
            __syncthreads();
        }

        // stage tau = 1/acc[k-1] (coalesced ldcg: L2-only, no stale L1)
        const float* accp = &g_acc[k - 1][b * N];
        {
            const int i0 = tid * 8;
            float4 a0 = __ldcg((const float4*)(accp + i0));
            float4 a1 = __ldcg((const float4*)(accp + i0 + 4));
            float4 t0 = {1.0f / fmaxf(a0.x, 1e-30f), 1.0f / fmaxf(a0.y, 1e-30f),
                         1.0f / fmaxf(a0.z, 1e-30f), 1.0f / fmaxf(a0.w, 1e-30f)};
            float4 t1 = {1.0f / fmaxf(a1.x, 1e-30f), 1.0f / fmaxf(a1.y, 1e-30f),
                         1.0f / fmaxf(a1.z, 1e-30f), 1.0f / fmaxf(a1.w, 1e-30f)};
            *(float4*)&s_tau[i0] = t0;
            *(float4*)&s_tau[i0 + 4] = t1;
        }
        __syncthreads();

        float* accn = &g_acc[k][b * N];
        float dot[RPW4];
        #pragma unroll
        for (int r = 0; r < RPW4; r++)
            dot[r] = v0[r] * s_tau[e0[r].x] + v1[r] * s_tau[e1[r].x];

        #pragma unroll
        for (int r = 0; r < RPW4; r++) {
            if (cnt[r] > 64) {
                const int2* sp = &g_sent[(size_t)(rbase + r) * CAP];
                #pragma unroll 1
                for (int s = lane + 64; s < cnt[r]; s += 64) {
                    const int2 f0 = sp[s], f1 = sp[s + 32];
                    dot[r] += __int_as_float(f0.y) * s_tau[f0.x]
                            + __int_as_float(f1.y) * s_tau[f1.x];
                }
            }
        }
        #pragma unroll
        for (int o = 16; o; o >>= 1) {
            #pragma unroll
            for (int r = 0; r < RPW4; r++)
                dot[r] += __shfl_xor_sync(0xffffffffu, dot[r], o);
        }
        float sig[RPW4];
        #pragma unroll
        for (int r = 0; r < RPW4; r++) sig[r] = 1.0f / dot[r];

        if (k == NITER && lane < RPW4)
            g_s[rbase + lane] = sig[0] * (lane == 0) + sig[1] * (lane == 1)
                              + sig[2] * (lane == 2) + sig[3] * (lane == 3);

        #pragma unroll
        for (int r = 0; r < RPW4; r++) {
            if (v0[r] > 0.0f) atomicAdd(accn + e0[r].x, v0[r] * sig[r]);
            if (v1[r] > 0.0f) atomicAdd(accn + e1[r].x, v1[r] * sig[r]);
        }
        #pragma unroll
        for (int r = 0; r < RPW4; r++) {
            if (cnt[r] > 64) {
                const int2* sp = &g_sent[(size_t)(rbase + r) * CAP];
                #pragma unroll 1
                for (int s = lane + 64; s < cnt[r]; s += 64) {
                    const int2 f0 = sp[s], f1 = sp[s + 32];
                    const float w0 = __int_as_float(f0.y), w1 = __int_as_float(f1.y);
                    if (w0 > 0.0f) atomicAdd(accn + f0.x, w0 * sig[r]);
                    if (w1 > 0.0f) atomicAdd(accn + f1.x, w1 * sig[r]);
                }
            }
        }

        // arrive: this CTA's scatters for iteration k are issued & release-fenced
        if (k < NITER) {
            __syncthreads();
            if (tid == 0) bar_arrive_release(&g_bar);
        }
    }
}

// K11 (R13 verbatim): out = exp(A*INVL - m_i) * s10_i * t10_j. 2-row prefetch.
__global__ void __launch_bounds__(TPB) final_kernel(const float* __restrict__ A,
                                                    float* __restrict__ out) {
    const int rbase = blockIdx.x * 8;
    const int b = rbase >> 11;
    const int col = threadIdx.x * 8;
    const float* accp = &g_acc[NITER][b * N + col];
    float tv[8];
    #pragma unroll
    for (int j = 0; j < 8; j++) tv[j] = 1.0f / fmaxf(accp[j], 1e-30f);

    const size_t off0 = (size_t)rbase * N + col;
    float4 x0 = *(const float4*)(A + off0);
    float4 x1 = *(const float4*)(A + off0 + 4);

    #pragma unroll 1
    for (int r = 0; r < 8; r++) {
        float4 n0, n1;
        if (r < 7) {
            const size_t offn = (size_t)(rbase + r + 1) * N + col;
            n0 = *(const float4*)(A + offn);
            n1 = *(const float4*)(A + offn + 4);
        }
        const int row = rbase + r;
        const float s = g_s[row];
        const float m = g_m[row];
        float a[8] = {x0.x, x0.y, x0.z, x0.w, x1.x, x1.y, x1.z, x1.w};
        float4 o0, o1;
        o0.x = __expf(fmaf(a[0], INVL, -m)) * s * tv[0];
        o0.y = __expf(fmaf(a[1], INVL, -m)) * s * tv[1];
        o0.z = __expf(fmaf(a[2], INVL, -m)) * s * tv[2];
        o0.w = __expf(fmaf(a[3], INVL, -m)) * s * tv[3];
        o1.x = __expf(fmaf(a[4], INVL, -m)) * s * tv[4];
        o1.y = __expf(fmaf(a[5], INVL, -m)) * s * tv[5];
        o1.z = __expf(fmaf(a[6], INVL, -m)) * s * tv[6];
        o1.w = __expf(fmaf(a[7], INVL, -m)) * s * tv[7];
        const size_t off = (size_t)row * N + col;
        *(float4*)(out + off) = o0;
        *(float4*)(out + off + 4) = o1;
        x0 = n0; x1 = n1;
    }
}

extern "C" void kernel_launch(void* const* d_in, const int* in_sizes, int n_in,
                              void* d_out, int out_size) {
    const float* A = (const float*)d_in[0];
    float* O = (float*)d_out;

    zero_kernel<<<(NITER * NROWS + TPB - 1) / TPB, TPB>>>();
    k1_kernel<<<GRID_BIG, TPB>>>(A);
    sparse_persist<<<NCTA, TPB>>>();          // iterations 2..10, one launch
    final_kernel<<<(BATCH * N) / 8, TPB>>>(A, O);
}